// round 3
// baseline (speedup 1.0000x reference)
#include <cuda_runtime.h>
#include <math.h>

#define ED    64      // embed dim
#define NKK   32      // w2 output dim
#define N_MAX 2048

// ---------------- device scratch (no allocations allowed) ----------------
// Rows 0..15 = subj, 16..24 = rel, 25..40 = obj. A = hi-side, B = hj-side.
__device__ float g_P[41 * ED];      // projected tables (stage 1)
__device__ float g_Atab[41 * ED];
__device__ float g_Btab[41 * ED];
// Transposed (d-major) per-row features: [d][n]
__device__ float g_HIt[ED * N_MAX];
__device__ float g_HJt[ED * N_MAX];

// ---------------- packed f32x2 helpers (FFMA2 only via PTX) ----------------
__device__ __forceinline__ unsigned long long pack2(float a, float b) {
    unsigned long long r;
    asm("mov.b64 %0, {%1, %2};" : "=l"(r) : "f"(a), "f"(b));
    return r;
}
__device__ __forceinline__ void unpack2(unsigned long long v, float &a, float &b) {
    asm("mov.b64 {%0, %1}, %2;" : "=f"(a), "=f"(b) : "l"(v));
}
__device__ __forceinline__ unsigned long long fma2(unsigned long long a,
                                                   unsigned long long b,
                                                   unsigned long long c) {
    unsigned long long d;
    asm("fma.rn.f32x2 %0, %1, %2, %3;" : "=l"(d) : "l"(a), "l"(b), "l"(c));
    return d;
}

__device__ __forceinline__ float warp_sum(float v) {
#pragma unroll
    for (int s = 16; s; s >>= 1) v += __shfl_xor_sync(0xffffffffu, v, s);
    return v;
}

// ---------------- stage P1: projected tables, one warp per output ----------
// P[row][k] = sum_m table[row][m] * proj_w[k][off+m]
__global__ void p1_kernel(const float* __restrict__ st,
                          const float* __restrict__ rt,
                          const float* __restrict__ ot,
                          const float* __restrict__ pw)   // [64][192]
{
    int warp = (blockIdx.x * blockDim.x + threadIdx.x) >> 5;
    int lane = threadIdx.x & 31;
    if (warp >= 41 * ED) return;
    int row = warp >> 6, k = warp & 63;
    const float* tab;
    int off;
    if (row < 16)      { tab = st + row * ED;        off = 0;   }
    else if (row < 25) { tab = rt + (row - 16) * ED; off = 64;  }
    else               { tab = ot + (row - 25) * ED; off = 128; }
    const float* wrow = pw + k * 192 + off;
    float v = tab[lane] * wrow[lane] + tab[lane + 32] * wrow[lane + 32];
    v = warp_sum(v);
    if (lane == 0) g_P[warp] = v;
}

// ---------------- stage P2: A/B tables, one warp per output ----------------
// A[row][d] = dot(P[row], w1a[d]);  B[row][d] = dot(P[row], w1b[d]).
// Obj rows (>=25) fold in the proj_b-propagated bias; B side also gets b1.
__global__ void p2_kernel(const float* __restrict__ pb,   // [64]
                          const float* __restrict__ w1,   // [64][128]
                          const float* __restrict__ b1)   // [64]
{
    int warp = (blockIdx.x * blockDim.x + threadIdx.x) >> 5;
    int lane = threadIdx.x & 31;
    if (warp >= 2 * 41 * ED) return;
    int side = warp / (41 * ED);
    int rem  = warp % (41 * ED);
    int row = rem >> 6, d = rem & 63;
    const float* w1row = w1 + d * 128 + side * 64;
    const float* Prow  = g_P + row * ED;
    float v = Prow[lane] * w1row[lane] + Prow[lane + 32] * w1row[lane + 32];
    if (row >= 25)
        v += pb[lane] * w1row[lane] + pb[lane + 32] * w1row[lane + 32];
    v = warp_sum(v);
    if (lane == 0) {
        if (row >= 25 && side == 1) v += b1[d];
        if (side) g_Btab[rem] = v;
        else      g_Atab[rem] = v;
    }
}

// ---------------- kernel B: gather -> HI/HJ in d-major layout --------------
__global__ void gather_kernel(const int* __restrict__ si,
                              const int* __restrict__ ri,
                              const int* __restrict__ oi, int n)
{
    int g = blockIdx.x * blockDim.x + threadIdx.x;
    int total = (ED / 4) * n;
    if (g >= total) return;
    int d4 = g / n;        // which group of 4 d's
    int nn = g % n;        // row index (consecutive across lanes -> coalesced)
    int c  = d4 * 4;
    int s = si[nn], r = ri[nn], o = oi[nn];

    float4 a0 = *(const float4*)&g_Atab[s * ED + c];
    float4 a1 = *(const float4*)&g_Atab[(16 + r) * ED + c];
    float4 a2 = *(const float4*)&g_Atab[(25 + o) * ED + c];
    g_HIt[(c + 0) * n + nn] = a0.x + a1.x + a2.x;
    g_HIt[(c + 1) * n + nn] = a0.y + a1.y + a2.y;
    g_HIt[(c + 2) * n + nn] = a0.z + a1.z + a2.z;
    g_HIt[(c + 3) * n + nn] = a0.w + a1.w + a2.w;

    float4 b0 = *(const float4*)&g_Btab[s * ED + c];
    float4 b1v = *(const float4*)&g_Btab[(16 + r) * ED + c];
    float4 b2v = *(const float4*)&g_Btab[(25 + o) * ED + c];
    g_HJt[(c + 0) * n + nn] = b0.x + b1v.x + b2v.x;
    g_HJt[(c + 1) * n + nn] = b0.y + b1v.y + b2v.y;
    g_HJt[(c + 2) * n + nn] = b0.z + b1v.z + b2v.z;
    g_HJt[(c + 3) * n + nn] = b0.w + b1v.w + b2v.w;
}

// ---------------- kernel C: pairwise scores, 32x32 tiles, FFMA2 ------------
// Thread layout: 256 threads = 32 i-rows x 8 j-quads; each thread owns
// (1 i) x (4 j) packed as two f32x2 lanes. k split in two passes of 16 to
// keep the accumulator at 32 x u64 registers.
__global__ void __launch_bounds__(256, 2)
score_kernel(const float* __restrict__ w2,   // [32][64]
             const float* __restrict__ b2,   // [32]
             const float* __restrict__ w3,   // [1][32]
             const float* __restrict__ b3,   // [1]
             float* __restrict__ out, int n)
{
    const int ti = blockIdx.y, tj = blockIdx.x;
    const int t  = threadIdx.x;
    const int il = t >> 3;          // local i row 0..31
    const int jq = t & 7;           // j quad 0..7
    const int i0 = ti * 32, j0 = tj * 32;

    if (tj < ti) {  // entire tile strictly below diagonal -> zeros only
        *(float4*)&out[(size_t)(i0 + il) * n + j0 + jq * 4] =
            make_float4(0.f, 0.f, 0.f, 0.f);
        return;
    }

    __shared__ __align__(16) float  sHI[ED][32];     // [d][i]
    __shared__ __align__(16) float  sHJ[ED][32];     // [d][j]
    __shared__ __align__(16) float2 sW2[ED][NKK];    // [d][k], duplicated (w,w)
    __shared__ float sw3[NKK], sb2[NKK];

#pragma unroll
    for (int r = 0; r < 2; r++) {                    // 512 float4s, 2/thread
        int idx = r * 256 + t;
        int row = idx >> 3, c4 = (idx & 7) * 4;
        *(float4*)&sHI[row][c4] = *(const float4*)&g_HIt[row * n + i0 + c4];
        *(float4*)&sHJ[row][c4] = *(const float4*)&g_HJt[row * n + j0 + c4];
    }
#pragma unroll
    for (int r = 0; r < 8; r++) {                    // 2048 w2 elems, 8/thread
        int idx = r * 256 + t;
        int d = idx >> 5, k = idx & 31;
        float w = w2[k * ED + d];
        sW2[d][k] = make_float2(w, w);
    }
    if (t < NKK) { sw3[t] = w3[t]; sb2[t] = b2[t]; }
    __syncthreads();

    float s0 = 0.f, s1 = 0.f, s2 = 0.f, s3 = 0.f;

#pragma unroll
    for (int pass = 0; pass < 2; pass++) {
        const int kb = pass * 16;
        unsigned long long acc0[16], acc1[16];
#pragma unroll
        for (int k = 0; k < 16; k++) { acc0[k] = 0ull; acc1[k] = 0ull; }

#pragma unroll 4
        for (int d = 0; d < ED; d++) {
            float  hi  = sHI[d][il];
            float4 hj4 = *(const float4*)&sHJ[d][jq * 4];
            float h0 = fmaxf(hi + hj4.x, 0.f);
            float h1 = fmaxf(hi + hj4.y, 0.f);
            float h2 = fmaxf(hi + hj4.z, 0.f);
            float h3 = fmaxf(hi + hj4.w, 0.f);
            unsigned long long H01 = pack2(h0, h1);
            unsigned long long H23 = pack2(h2, h3);
#pragma unroll
            for (int k = 0; k < 16; k++) {
                unsigned long long w =
                    *(const unsigned long long*)&sW2[d][kb + k];
                acc0[k] = fma2(H01, w, acc0[k]);
                acc1[k] = fma2(H23, w, acc1[k]);
            }
        }

#pragma unroll
        for (int k = 0; k < 16; k++) {
            float a0, a1, a2, a3;
            unpack2(acc0[k], a0, a1);
            unpack2(acc1[k], a2, a3);
            float bb = sb2[kb + k], ww = sw3[kb + k];
            s0 += fmaxf(a0 + bb, 0.f) * ww;
            s1 += fmaxf(a1 + bb, 0.f) * ww;
            s2 += fmaxf(a2 + bb, 0.f) * ww;
            s3 += fmaxf(a3 + bb, 0.f) * ww;
        }
    }

    const float bb3 = b3[0];
    const int i  = i0 + il;
    const int jb = j0 + jq * 4;
    float4 r;
    r.x = (jb + 0 > i) ? 1.f / (1.f + __expf(-(s0 + bb3))) : 0.f;
    r.y = (jb + 1 > i) ? 1.f / (1.f + __expf(-(s1 + bb3))) : 0.f;
    r.z = (jb + 2 > i) ? 1.f / (1.f + __expf(-(s2 + bb3))) : 0.f;
    r.w = (jb + 3 > i) ? 1.f / (1.f + __expf(-(s3 + bb3))) : 0.f;
    *(float4*)&out[(size_t)i * n + jb] = r;
}

// ---------------- launch ----------------------------------------------------
extern "C" void kernel_launch(void* const* d_in, const int* in_sizes, int n_in,
                              void* d_out, int out_size)
{
    const int*   si = (const int*)d_in[0];
    const int*   ri = (const int*)d_in[1];
    const int*   oi = (const int*)d_in[2];
    const float* st = (const float*)d_in[3];
    const float* rt = (const float*)d_in[4];
    const float* ot = (const float*)d_in[5];
    const float* pw = (const float*)d_in[6];
    const float* pb = (const float*)d_in[7];
    const float* w1 = (const float*)d_in[8];
    const float* b1 = (const float*)d_in[9];
    const float* w2 = (const float*)d_in[10];
    const float* b2 = (const float*)d_in[11];
    const float* w3 = (const float*)d_in[12];
    const float* b3 = (const float*)d_in[13];
    float* out = (float*)d_out;
    const int n = in_sizes[0];

    // P1: one warp per projected-table element (41*64 outputs)
    p1_kernel<<<(41 * ED * 32 + 255) / 256, 256>>>(st, rt, ot, pw);
    // P2: one warp per A/B-table element (2*41*64 outputs)
    p2_kernel<<<(2 * 41 * ED * 32 + 255) / 256, 256>>>(pb, w1, b1);

    int total = (ED / 4) * n;
    gather_kernel<<<(total + 255) / 256, 256>>>(si, ri, oi, n);

    dim3 grid(n / 32, n / 32);
    score_kernel<<<grid, 256>>>(w2, b2, w3, b3, out, n);
}

// round 4
// speedup vs baseline: 1.0018x; 1.0018x over previous
#include <cuda_runtime.h>
#include <math.h>

#define ED    64      // embed dim
#define NKK   32      // w2 output dim
#define N_MAX 2048

// ---------------- device scratch (no allocations allowed) ----------------
// Rows 0..15 = subj, 16..24 = rel, 25..40 = obj. A = hi-side, B = hj-side.
__device__ float g_P[41 * ED];      // projected tables (stage 1)
__device__ float g_Atab[41 * ED];
__device__ float g_Btab[41 * ED];
// Transposed (d-major) per-row features: [d][n]
__device__ float g_HIt[ED * N_MAX];
__device__ float g_HJt[ED * N_MAX];

// ---------------- packed f32x2 helpers (FFMA2 only via PTX) ----------------
__device__ __forceinline__ unsigned long long pack2(float a, float b) {
    unsigned long long r;
    asm("mov.b64 %0, {%1, %2};" : "=l"(r) : "f"(a), "f"(b));
    return r;
}
__device__ __forceinline__ void unpack2(unsigned long long v, float &a, float &b) {
    asm("mov.b64 {%0, %1}, %2;" : "=f"(a), "=f"(b) : "l"(v));
}
__device__ __forceinline__ unsigned long long fma2(unsigned long long a,
                                                   unsigned long long b,
                                                   unsigned long long c) {
    unsigned long long d;
    asm("fma.rn.f32x2 %0, %1, %2, %3;" : "=l"(d) : "l"(a), "l"(b), "l"(c));
    return d;
}

__device__ __forceinline__ float warp_sum(float v) {
#pragma unroll
    for (int s = 16; s; s >>= 1) v += __shfl_xor_sync(0xffffffffu, v, s);
    return v;
}

// ---------------- stage P1: projected tables, one warp per output ----------
// P[row][k] = sum_m table[row][m] * proj_w[k][off+m]
__global__ void p1_kernel(const float* __restrict__ st,
                          const float* __restrict__ rt,
                          const float* __restrict__ ot,
                          const float* __restrict__ pw)   // [64][192]
{
    int warp = (blockIdx.x * blockDim.x + threadIdx.x) >> 5;
    int lane = threadIdx.x & 31;
    if (warp >= 41 * ED) return;
    int row = warp >> 6, k = warp & 63;
    const float* tab;
    int off;
    if (row < 16)      { tab = st + row * ED;        off = 0;   }
    else if (row < 25) { tab = rt + (row - 16) * ED; off = 64;  }
    else               { tab = ot + (row - 25) * ED; off = 128; }
    const float* wrow = pw + k * 192 + off;
    float v = tab[lane] * wrow[lane] + tab[lane + 32] * wrow[lane + 32];
    v = warp_sum(v);
    if (lane == 0) g_P[warp] = v;
}

// ---------------- stage P2: A/B tables, one warp per output ----------------
// A[row][d] = dot(P[row], w1a[d]);  B[row][d] = dot(P[row], w1b[d]).
// Obj rows (>=25) fold in the proj_b-propagated bias; B side also gets b1.
__global__ void p2_kernel(const float* __restrict__ pb,   // [64]
                          const float* __restrict__ w1,   // [64][128]
                          const float* __restrict__ b1)   // [64]
{
    int warp = (blockIdx.x * blockDim.x + threadIdx.x) >> 5;
    int lane = threadIdx.x & 31;
    if (warp >= 2 * 41 * ED) return;
    int side = warp / (41 * ED);
    int rem  = warp % (41 * ED);
    int row = rem >> 6, d = rem & 63;
    const float* w1row = w1 + d * 128 + side * 64;
    const float* Prow  = g_P + row * ED;
    float v = Prow[lane] * w1row[lane] + Prow[lane + 32] * w1row[lane + 32];
    if (row >= 25)
        v += pb[lane] * w1row[lane] + pb[lane + 32] * w1row[lane + 32];
    v = warp_sum(v);
    if (lane == 0) {
        if (row >= 25 && side == 1) v += b1[d];
        if (side) g_Btab[rem] = v;
        else      g_Atab[rem] = v;
    }
}

// ---------------- kernel B: gather -> HI/HJ in d-major layout --------------
__global__ void gather_kernel(const int* __restrict__ si,
                              const int* __restrict__ ri,
                              const int* __restrict__ oi, int n)
{
    int g = blockIdx.x * blockDim.x + threadIdx.x;
    int total = (ED / 4) * n;
    if (g >= total) return;
    int d4 = g / n;        // which group of 4 d's
    int nn = g % n;        // row index (consecutive across lanes -> coalesced)
    int c  = d4 * 4;
    int s = si[nn], r = ri[nn], o = oi[nn];

    float4 a0 = *(const float4*)&g_Atab[s * ED + c];
    float4 a1 = *(const float4*)&g_Atab[(16 + r) * ED + c];
    float4 a2 = *(const float4*)&g_Atab[(25 + o) * ED + c];
    g_HIt[(c + 0) * n + nn] = a0.x + a1.x + a2.x;
    g_HIt[(c + 1) * n + nn] = a0.y + a1.y + a2.y;
    g_HIt[(c + 2) * n + nn] = a0.z + a1.z + a2.z;
    g_HIt[(c + 3) * n + nn] = a0.w + a1.w + a2.w;

    float4 b0 = *(const float4*)&g_Btab[s * ED + c];
    float4 b1v = *(const float4*)&g_Btab[(16 + r) * ED + c];
    float4 b2v = *(const float4*)&g_Btab[(25 + o) * ED + c];
    g_HJt[(c + 0) * n + nn] = b0.x + b1v.x + b2v.x;
    g_HJt[(c + 1) * n + nn] = b0.y + b1v.y + b2v.y;
    g_HJt[(c + 2) * n + nn] = b0.z + b1v.z + b2v.z;
    g_HJt[(c + 3) * n + nn] = b0.w + b1v.w + b2v.w;
}

// ---------------- kernel C: pairwise scores, 32x32 tiles, FFMA2 ------------
// Thread layout: 256 threads = 32 i-rows x 8 j-quads; each thread owns
// (1 i) x (4 j) packed as two f32x2 lanes. k split in two passes of 16 to
// keep the accumulator at 32 x u64 registers.
__global__ void __launch_bounds__(256, 2)
score_kernel(const float* __restrict__ w2,   // [32][64]
             const float* __restrict__ b2,   // [32]
             const float* __restrict__ w3,   // [1][32]
             const float* __restrict__ b3,   // [1]
             float* __restrict__ out, int n)
{
    const int ti = blockIdx.y, tj = blockIdx.x;
    const int t  = threadIdx.x;
    const int il = t >> 3;          // local i row 0..31
    const int jq = t & 7;           // j quad 0..7
    const int i0 = ti * 32, j0 = tj * 32;

    if (tj < ti) {  // entire tile strictly below diagonal -> zeros only
        *(float4*)&out[(size_t)(i0 + il) * n + j0 + jq * 4] =
            make_float4(0.f, 0.f, 0.f, 0.f);
        return;
    }

    __shared__ __align__(16) float  sHI[ED][32];     // [d][i]
    __shared__ __align__(16) float  sHJ[ED][32];     // [d][j]
    __shared__ __align__(16) float2 sW2[ED][NKK];    // [d][k], duplicated (w,w)
    __shared__ float sw3[NKK], sb2[NKK];

#pragma unroll
    for (int r = 0; r < 2; r++) {                    // 512 float4s, 2/thread
        int idx = r * 256 + t;
        int row = idx >> 3, c4 = (idx & 7) * 4;
        *(float4*)&sHI[row][c4] = *(const float4*)&g_HIt[row * n + i0 + c4];
        *(float4*)&sHJ[row][c4] = *(const float4*)&g_HJt[row * n + j0 + c4];
    }
#pragma unroll
    for (int r = 0; r < 8; r++) {                    // 2048 w2 elems, 8/thread
        int idx = r * 256 + t;
        int d = idx >> 5, k = idx & 31;
        float w = w2[k * ED + d];
        sW2[d][k] = make_float2(w, w);
    }
    if (t < NKK) { sw3[t] = w3[t]; sb2[t] = b2[t]; }
    __syncthreads();

    float s0 = 0.f, s1 = 0.f, s2 = 0.f, s3 = 0.f;

#pragma unroll
    for (int pass = 0; pass < 2; pass++) {
        const int kb = pass * 16;
        unsigned long long acc0[16], acc1[16];
#pragma unroll
        for (int k = 0; k < 16; k++) { acc0[k] = 0ull; acc1[k] = 0ull; }

#pragma unroll 4
        for (int d = 0; d < ED; d++) {
            float  hi  = sHI[d][il];
            float4 hj4 = *(const float4*)&sHJ[d][jq * 4];
            float h0 = fmaxf(hi + hj4.x, 0.f);
            float h1 = fmaxf(hi + hj4.y, 0.f);
            float h2 = fmaxf(hi + hj4.z, 0.f);
            float h3 = fmaxf(hi + hj4.w, 0.f);
            unsigned long long H01 = pack2(h0, h1);
            unsigned long long H23 = pack2(h2, h3);
#pragma unroll
            for (int k = 0; k < 16; k++) {
                unsigned long long w =
                    *(const unsigned long long*)&sW2[d][kb + k];
                acc0[k] = fma2(H01, w, acc0[k]);
                acc1[k] = fma2(H23, w, acc1[k]);
            }
        }

#pragma unroll
        for (int k = 0; k < 16; k++) {
            float a0, a1, a2, a3;
            unpack2(acc0[k], a0, a1);
            unpack2(acc1[k], a2, a3);
            float bb = sb2[kb + k], ww = sw3[kb + k];
            s0 += fmaxf(a0 + bb, 0.f) * ww;
            s1 += fmaxf(a1 + bb, 0.f) * ww;
            s2 += fmaxf(a2 + bb, 0.f) * ww;
            s3 += fmaxf(a3 + bb, 0.f) * ww;
        }
    }

    const float bb3 = b3[0];
    const int i  = i0 + il;
    const int jb = j0 + jq * 4;
    float4 r;
    r.x = (jb + 0 > i) ? 1.f / (1.f + __expf(-(s0 + bb3))) : 0.f;
    r.y = (jb + 1 > i) ? 1.f / (1.f + __expf(-(s1 + bb3))) : 0.f;
    r.z = (jb + 2 > i) ? 1.f / (1.f + __expf(-(s2 + bb3))) : 0.f;
    r.w = (jb + 3 > i) ? 1.f / (1.f + __expf(-(s3 + bb3))) : 0.f;
    *(float4*)&out[(size_t)i * n + jb] = r;
}

// ---------------- launch ----------------------------------------------------
extern "C" void kernel_launch(void* const* d_in, const int* in_sizes, int n_in,
                              void* d_out, int out_size)
{
    const int*   si = (const int*)d_in[0];
    const int*   ri = (const int*)d_in[1];
    const int*   oi = (const int*)d_in[2];
    const float* st = (const float*)d_in[3];
    const float* rt = (const float*)d_in[4];
    const float* ot = (const float*)d_in[5];
    const float* pw = (const float*)d_in[6];
    const float* pb = (const float*)d_in[7];
    const float* w1 = (const float*)d_in[8];
    const float* b1 = (const float*)d_in[9];
    const float* w2 = (const float*)d_in[10];
    const float* b2 = (const float*)d_in[11];
    const float* w3 = (const float*)d_in[12];
    const float* b3 = (const float*)d_in[13];
    float* out = (float*)d_out;
    const int n = in_sizes[0];

    // P1: one warp per projected-table element (41*64 outputs)
    p1_kernel<<<(41 * ED * 32 + 255) / 256, 256>>>(st, rt, ot, pw);
    // P2: one warp per A/B-table element (2*41*64 outputs)
    p2_kernel<<<(2 * 41 * ED * 32 + 255) / 256, 256>>>(pb, w1, b1);

    int total = (ED / 4) * n;
    gather_kernel<<<(total + 255) / 256, 256>>>(si, ri, oi, n);

    dim3 grid(n / 32, n / 32);
    score_kernel<<<grid, 256>>>(w2, b2, w3, b3, out, n);
}

// round 5
// speedup vs baseline: 1.0063x; 1.0046x over previous
#include <cuda_runtime.h>
#include <math.h>

#define ED    64      // embed dim
#define NKK   32      // w2 output dim
#define N_MAX 2048

// ---------------- device scratch (no allocations allowed) ----------------
// Rows 0..15 = subj, 16..24 = rel, 25..40 = obj. A = hi-side, B = hj-side.
__device__ float g_P[41 * ED];      // projected tables (stage 1)
__device__ float g_Atab[41 * ED];
__device__ float g_Btab[41 * ED];
// Transposed (d-major) per-row features: [d][n]
__device__ float g_HIt[ED * N_MAX];
__device__ float g_HJt[ED * N_MAX];

// ---------------- packed f32x2 helpers (FFMA2 only via PTX) ----------------
__device__ __forceinline__ unsigned long long pack2(float a, float b) {
    unsigned long long r;
    asm("mov.b64 %0, {%1, %2};" : "=l"(r) : "f"(a), "f"(b));
    return r;
}
__device__ __forceinline__ void unpack2(unsigned long long v, float &a, float &b) {
    asm("mov.b64 {%0, %1}, %2;" : "=f"(a), "=f"(b) : "l"(v));
}
__device__ __forceinline__ unsigned long long fma2(unsigned long long a,
                                                   unsigned long long b,
                                                   unsigned long long c) {
    unsigned long long d;
    asm("fma.rn.f32x2 %0, %1, %2, %3;" : "=l"(d) : "l"(a), "l"(b), "l"(c));
    return d;
}

__device__ __forceinline__ float warp_sum(float v) {
#pragma unroll
    for (int s = 16; s; s >>= 1) v += __shfl_xor_sync(0xffffffffu, v, s);
    return v;
}

// ---------------- stage P1: projected tables, one warp per output ----------
// P[row][k] = sum_m table[row][m] * proj_w[k][off+m]
__global__ void p1_kernel(const float* __restrict__ st,
                          const float* __restrict__ rt,
                          const float* __restrict__ ot,
                          const float* __restrict__ pw)   // [64][192]
{
    int warp = (blockIdx.x * blockDim.x + threadIdx.x) >> 5;
    int lane = threadIdx.x & 31;
    if (warp >= 41 * ED) return;
    int row = warp >> 6, k = warp & 63;
    const float* tab;
    int off;
    if (row < 16)      { tab = st + row * ED;        off = 0;   }
    else if (row < 25) { tab = rt + (row - 16) * ED; off = 64;  }
    else               { tab = ot + (row - 25) * ED; off = 128; }
    const float* wrow = pw + k * 192 + off;
    float v = tab[lane] * wrow[lane] + tab[lane + 32] * wrow[lane + 32];
    v = warp_sum(v);
    if (lane == 0) g_P[warp] = v;
}

// ---------------- stage P2: A/B tables, one warp per output ----------------
// A[row][d] = dot(P[row], w1a[d]);  B[row][d] = dot(P[row], w1b[d]).
// Obj rows (>=25) fold in the proj_b-propagated bias; B side also gets b1.
__global__ void p2_kernel(const float* __restrict__ pb,   // [64]
                          const float* __restrict__ w1,   // [64][128]
                          const float* __restrict__ b1)   // [64]
{
    int warp = (blockIdx.x * blockDim.x + threadIdx.x) >> 5;
    int lane = threadIdx.x & 31;
    if (warp >= 2 * 41 * ED) return;
    int side = warp / (41 * ED);
    int rem  = warp % (41 * ED);
    int row = rem >> 6, d = rem & 63;
    const float* w1row = w1 + d * 128 + side * 64;
    const float* Prow  = g_P + row * ED;
    float v = Prow[lane] * w1row[lane] + Prow[lane + 32] * w1row[lane + 32];
    if (row >= 25)
        v += pb[lane] * w1row[lane] + pb[lane + 32] * w1row[lane + 32];
    v = warp_sum(v);
    if (lane == 0) {
        if (row >= 25 && side == 1) v += b1[d];
        if (side) g_Btab[rem] = v;
        else      g_Atab[rem] = v;
    }
}

// ---------------- kernel B: gather -> HI/HJ in d-major layout --------------
__global__ void gather_kernel(const int* __restrict__ si,
                              const int* __restrict__ ri,
                              const int* __restrict__ oi, int n)
{
    int g = blockIdx.x * blockDim.x + threadIdx.x;
    int total = (ED / 4) * n;
    if (g >= total) return;
    int d4 = g / n;        // which group of 4 d's
    int nn = g % n;        // row index (consecutive across lanes -> coalesced)
    int c  = d4 * 4;
    int s = si[nn], r = ri[nn], o = oi[nn];

    float4 a0 = *(const float4*)&g_Atab[s * ED + c];
    float4 a1 = *(const float4*)&g_Atab[(16 + r) * ED + c];
    float4 a2 = *(const float4*)&g_Atab[(25 + o) * ED + c];
    g_HIt[(c + 0) * n + nn] = a0.x + a1.x + a2.x;
    g_HIt[(c + 1) * n + nn] = a0.y + a1.y + a2.y;
    g_HIt[(c + 2) * n + nn] = a0.z + a1.z + a2.z;
    g_HIt[(c + 3) * n + nn] = a0.w + a1.w + a2.w;

    float4 b0 = *(const float4*)&g_Btab[s * ED + c];
    float4 b1v = *(const float4*)&g_Btab[(16 + r) * ED + c];
    float4 b2v = *(const float4*)&g_Btab[(25 + o) * ED + c];
    g_HJt[(c + 0) * n + nn] = b0.x + b1v.x + b2v.x;
    g_HJt[(c + 1) * n + nn] = b0.y + b1v.y + b2v.y;
    g_HJt[(c + 2) * n + nn] = b0.z + b1v.z + b2v.z;
    g_HJt[(c + 3) * n + nn] = b0.w + b1v.w + b2v.w;
}

// ---------------- kernel C: pairwise scores, 32x32 tiles, FFMA2 ------------
// Thread layout: 256 threads = 32 i-rows x 8 j-quads; each thread owns
// (1 i) x (4 j) packed as two f32x2 lanes. k split in two passes of 16 to
// keep the accumulator at 32 x u64 registers.
__global__ void __launch_bounds__(256, 2)
score_kernel(const float* __restrict__ w2,   // [32][64]
             const float* __restrict__ b2,   // [32]
             const float* __restrict__ w3,   // [1][32]
             const float* __restrict__ b3,   // [1]
             float* __restrict__ out, int n)
{
    const int ti = blockIdx.y, tj = blockIdx.x;
    const int t  = threadIdx.x;
    const int il = t >> 3;          // local i row 0..31
    const int jq = t & 7;           // j quad 0..7
    const int i0 = ti * 32, j0 = tj * 32;

    if (tj < ti) {  // entire tile strictly below diagonal -> zeros only
        *(float4*)&out[(size_t)(i0 + il) * n + j0 + jq * 4] =
            make_float4(0.f, 0.f, 0.f, 0.f);
        return;
    }

    __shared__ __align__(16) float  sHI[ED][32];     // [d][i]
    __shared__ __align__(16) float  sHJ[ED][32];     // [d][j]
    __shared__ __align__(16) float2 sW2[ED][NKK];    // [d][k], duplicated (w,w)
    __shared__ float sw3[NKK], sb2[NKK];

#pragma unroll
    for (int r = 0; r < 2; r++) {                    // 512 float4s, 2/thread
        int idx = r * 256 + t;
        int row = idx >> 3, c4 = (idx & 7) * 4;
        *(float4*)&sHI[row][c4] = *(const float4*)&g_HIt[row * n + i0 + c4];
        *(float4*)&sHJ[row][c4] = *(const float4*)&g_HJt[row * n + j0 + c4];
    }
#pragma unroll
    for (int r = 0; r < 8; r++) {                    // 2048 w2 elems, 8/thread
        int idx = r * 256 + t;
        int d = idx >> 5, k = idx & 31;
        float w = w2[k * ED + d];
        sW2[d][k] = make_float2(w, w);
    }
    if (t < NKK) { sw3[t] = w3[t]; sb2[t] = b2[t]; }
    __syncthreads();

    float s0 = 0.f, s1 = 0.f, s2 = 0.f, s3 = 0.f;

#pragma unroll
    for (int pass = 0; pass < 2; pass++) {
        const int kb = pass * 16;
        unsigned long long acc0[16], acc1[16];
#pragma unroll
        for (int k = 0; k < 16; k++) { acc0[k] = 0ull; acc1[k] = 0ull; }

#pragma unroll 4
        for (int d = 0; d < ED; d++) {
            float  hi  = sHI[d][il];
            float4 hj4 = *(const float4*)&sHJ[d][jq * 4];
            float h0 = fmaxf(hi + hj4.x, 0.f);
            float h1 = fmaxf(hi + hj4.y, 0.f);
            float h2 = fmaxf(hi + hj4.z, 0.f);
            float h3 = fmaxf(hi + hj4.w, 0.f);
            unsigned long long H01 = pack2(h0, h1);
            unsigned long long H23 = pack2(h2, h3);
#pragma unroll
            for (int k = 0; k < 16; k++) {
                unsigned long long w =
                    *(const unsigned long long*)&sW2[d][kb + k];
                acc0[k] = fma2(H01, w, acc0[k]);
                acc1[k] = fma2(H23, w, acc1[k]);
            }
        }

#pragma unroll
        for (int k = 0; k < 16; k++) {
            float a0, a1, a2, a3;
            unpack2(acc0[k], a0, a1);
            unpack2(acc1[k], a2, a3);
            float bb = sb2[kb + k], ww = sw3[kb + k];
            s0 += fmaxf(a0 + bb, 0.f) * ww;
            s1 += fmaxf(a1 + bb, 0.f) * ww;
            s2 += fmaxf(a2 + bb, 0.f) * ww;
            s3 += fmaxf(a3 + bb, 0.f) * ww;
        }
    }

    const float bb3 = b3[0];
    const int i  = i0 + il;
    const int jb = j0 + jq * 4;
    float4 r;
    r.x = (jb + 0 > i) ? 1.f / (1.f + __expf(-(s0 + bb3))) : 0.f;
    r.y = (jb + 1 > i) ? 1.f / (1.f + __expf(-(s1 + bb3))) : 0.f;
    r.z = (jb + 2 > i) ? 1.f / (1.f + __expf(-(s2 + bb3))) : 0.f;
    r.w = (jb + 3 > i) ? 1.f / (1.f + __expf(-(s3 + bb3))) : 0.f;
    *(float4*)&out[(size_t)i * n + jb] = r;
}

// ---------------- launch ----------------------------------------------------
extern "C" void kernel_launch(void* const* d_in, const int* in_sizes, int n_in,
                              void* d_out, int out_size)
{
    const int*   si = (const int*)d_in[0];
    const int*   ri = (const int*)d_in[1];
    const int*   oi = (const int*)d_in[2];
    const float* st = (const float*)d_in[3];
    const float* rt = (const float*)d_in[4];
    const float* ot = (const float*)d_in[5];
    const float* pw = (const float*)d_in[6];
    const float* pb = (const float*)d_in[7];
    const float* w1 = (const float*)d_in[8];
    const float* b1 = (const float*)d_in[9];
    const float* w2 = (const float*)d_in[10];
    const float* b2 = (const float*)d_in[11];
    const float* w3 = (const float*)d_in[12];
    const float* b3 = (const float*)d_in[13];
    float* out = (float*)d_out;
    const int n = in_sizes[0];

    // P1: one warp per projected-table element (41*64 outputs)
    p1_kernel<<<(41 * ED * 32 + 255) / 256, 256>>>(st, rt, ot, pw);
    // P2: one warp per A/B-table element (2*41*64 outputs)
    p2_kernel<<<(2 * 41 * ED * 32 + 255) / 256, 256>>>(pb, w1, b1);

    int total = (ED / 4) * n;
    gather_kernel<<<(total + 255) / 256, 256>>>(si, ri, oi, n);

    dim3 grid(n / 32, n / 32);
    score_kernel<<<grid, 256>>>(w2, b2, w3, b3, out, n);
}